// round 1
// baseline (speedup 1.0000x reference)
#include <cuda_runtime.h>
#include <math.h>

#define B_SZ   32
#define D_IN   2
#define L_SEQ  4096
#define H_DIM  128
#define NL     6
#define NC     32
#define D_OUT  2
#define NSEQ   (B_SZ * H_DIM)        // 4096
#define CHUNKS 8
#define CHLEN  (L_SEQ / CHUNKS)      // 512
#define SPT    16                    // states per thread (2 threads per seq-chunk)
#define LT     16                    // l-tile for GLU kernel

// ---------------- scratch (static device arrays; no allocation) ----------------
__device__ float  g_h[NSEQ * L_SEQ];                 // current activations (B,H,L)
__device__ float  g_y[NSEQ * L_SEQ];                 // SSM output post-gelu (B,H,L)
__device__ float2 g_E[NSEQ * (CHUNKS - 1) * NC];     // chunk-end states
__device__ float  g_par[NL * 6 * H_DIM * NC];        // wre,wim,c2re,c2im,wpre,wpim
__device__ float  g_Wt[NL * H_DIM * 2 * H_DIM];      // transposed out_W: [layer][k][o]
__device__ float  g_pooled[NSEQ];

// ---------------- per-layer parameter precompute (double for accuracy) ----------
__global__ void param_kernel(const float* __restrict__ log_dt,
                             const float* __restrict__ C_re,
                             const float* __restrict__ C_im,
                             const float* __restrict__ log_A_real,
                             const float* __restrict__ A_imag) {
    int t = blockIdx.x * blockDim.x + threadIdx.x;
    if (t >= NL * H_DIM * NC) return;
    int layer = t / (H_DIM * NC);
    int hn    = t % (H_DIM * NC);
    int h     = hn / NC;

    double dt  = exp((double)log_dt[layer * H_DIM + h]);
    double Are = -exp((double)log_A_real[t]);
    double Aim = (double)A_imag[t];
    double xre = Are * dt, xim = Aim * dt;

    double ex = exp(xre);
    double sy, cy;
    sincos(xim, &sy, &cy);
    double wre = ex * cy, wim = ex * sy;

    // expm1(dtA), complex
    double em1re = ex * cy - 1.0;
    double em1im = ex * sy;

    // (C_re + i C_im) * expm1(dtA) / A, folded with factor 2
    double den = Are * Are + Aim * Aim;
    double fre = (em1re * Are + em1im * Aim) / den;
    double fim = (em1im * Are - em1re * Aim) / den;
    double cre = (double)C_re[t], cim = (double)C_im[t];
    double c2re = 2.0 * (cre * fre - cim * fim);
    double c2im = 2.0 * (cre * fim + cim * fre);

    // w^CHLEN for the chunk scan
    double pre = exp(xre * (double)CHLEN);
    double ps, pc;
    sincos(xim * (double)CHLEN, &ps, &pc);

    int S = H_DIM * NC;
    int base = layer * 6 * S + hn;
    g_par[base]         = (float)wre;
    g_par[base + S]     = (float)wim;
    g_par[base + 2 * S] = (float)c2re;
    g_par[base + 3 * S] = (float)c2im;
    g_par[base + 4 * S] = (float)(pre * pc);
    g_par[base + 5 * S] = (float)(pre * ps);
}

// ---------------- transpose out_W -> [layer][k][o] ----------------
__global__ void wt_kernel(const float* __restrict__ out_W) {
    int t = blockIdx.x * blockDim.x + threadIdx.x;
    if (t >= NL * 2 * H_DIM * H_DIM) return;
    int layer = t / (2 * H_DIM * H_DIM);
    int r     = t % (2 * H_DIM * H_DIM);
    int o = r / H_DIM;
    int k = r % H_DIM;
    g_Wt[layer * 2 * H_DIM * H_DIM + k * 2 * H_DIM + o] = out_W[t];
}

// ---------------- encoder: h[b,h,l] = x[b,0,l]*W[0,h] + x[b,1,l]*W[1,h] + b[h] ----
__global__ void enc_kernel(const float* __restrict__ x,
                           const float* __restrict__ enc_W,
                           const float* __restrict__ enc_b) {
    int t = blockIdx.x * blockDim.x + threadIdx.x;
    if (t >= NSEQ * (L_SEQ / 4)) return;
    int l4  = t % (L_SEQ / 4);
    int seq = t / (L_SEQ / 4);
    int b = seq / H_DIM;
    int h = seq % H_DIM;
    float w0 = enc_W[h];
    float w1 = enc_W[H_DIM + h];
    float bb = enc_b[h];
    float4 a = ((const float4*)(x + (b * D_IN + 0) * L_SEQ))[l4];
    float4 c = ((const float4*)(x + (b * D_IN + 1) * L_SEQ))[l4];
    float4 r;
    r.x = fmaf(w1, c.x, fmaf(w0, a.x, bb));
    r.y = fmaf(w1, c.y, fmaf(w0, a.y, bb));
    r.z = fmaf(w1, c.z, fmaf(w0, a.z, bb));
    r.w = fmaf(w1, c.w, fmaf(w0, a.w, bb));
    ((float4*)(g_h + seq * L_SEQ))[l4] = r;
}

// ---------------- pass 1: zero-init chunk-end states, chunks 0..CHUNKS-2 --------
__global__ void pass1_kernel(int layer) {
    int gid  = blockIdx.x * blockDim.x + threadIdx.x;
    int pair = gid >> 1;
    int half = gid & 1;
    int chunk = pair % (CHUNKS - 1);
    int seq   = pair / (CHUNKS - 1);
    int h = seq % H_DIM;

    const float* par = g_par + layer * 6 * H_DIM * NC;
    int S  = H_DIM * NC;
    int pb = h * NC + half * SPT;

    float wre[SPT], wim[SPT], sre[SPT], sim[SPT];
#pragma unroll
    for (int j = 0; j < SPT; j++) {
        wre[j] = par[pb + j];
        wim[j] = par[S + pb + j];
        sre[j] = 0.f; sim[j] = 0.f;
    }

    const float4* u4 = (const float4*)(g_h + seq * L_SEQ + chunk * CHLEN);
    for (int l = 0; l < CHLEN / 4; l++) {
        float4 u = u4[l];
        float uu[4] = {u.x, u.y, u.z, u.w};
#pragma unroll
        for (int q = 0; q < 4; q++) {
            float uv = uu[q];
#pragma unroll
            for (int j = 0; j < SPT; j++) {
                float nr = fmaf(-wim[j], sim[j], fmaf(wre[j], sre[j], uv));
                float ni = fmaf(wre[j], sim[j], wim[j] * sre[j]);
                sre[j] = nr; sim[j] = ni;
            }
        }
    }

    float2* E = g_E + (seq * (CHUNKS - 1) + chunk) * NC + half * SPT;
#pragma unroll
    for (int j = 0; j < SPT; j++) E[j] = make_float2(sre[j], sim[j]);
}

// ---------------- pass 2: exact recurrence + D skip + gelu -> g_y ----------------
__global__ void pass2_kernel(int layer, const float* __restrict__ Dvec) {
    int gid  = blockIdx.x * blockDim.x + threadIdx.x;
    int pair = gid >> 1;
    int half = gid & 1;
    int seq   = pair / CHUNKS;
    int chunk = pair % CHUNKS;
    int h = seq % H_DIM;

    const float* par = g_par + layer * 6 * H_DIM * NC;
    int S  = H_DIM * NC;
    int pb = h * NC + half * SPT;

    float sre[SPT], sim[SPT];
#pragma unroll
    for (int j = 0; j < SPT; j++) { sre[j] = 0.f; sim[j] = 0.f; }

    if (chunk > 0) {
        float wpre[SPT], wpim[SPT];
#pragma unroll
        for (int j = 0; j < SPT; j++) {
            wpre[j] = par[4 * S + pb + j];
            wpim[j] = par[5 * S + pb + j];
        }
        for (int c = 0; c < chunk; c++) {
            const float2* E = g_E + (seq * (CHUNKS - 1) + c) * NC + half * SPT;
#pragma unroll
            for (int j = 0; j < SPT; j++) {
                float2 e = E[j];
                float nr = fmaf(-wpim[j], sim[j], fmaf(wpre[j], sre[j], e.x));
                float ni = fmaf(wpre[j], sim[j], fmaf(wpim[j], sre[j], e.y));
                sre[j] = nr; sim[j] = ni;
            }
        }
    }

    float wre[SPT], wim[SPT], cr[SPT], ci[SPT];
#pragma unroll
    for (int j = 0; j < SPT; j++) {
        wre[j] = par[pb + j];
        wim[j] = par[S + pb + j];
        cr[j]  = par[2 * S + pb + j];
        ci[j]  = par[3 * S + pb + j];
    }
    float Dh = Dvec[layer * H_DIM + h];

    const float4* u4 = (const float4*)(g_h + seq * L_SEQ + chunk * CHLEN);
    float4*       y4 = (float4*)(g_y + seq * L_SEQ + chunk * CHLEN);

    for (int l = 0; l < CHLEN / 4; l++) {
        float4 u = u4[l];
        float uu[4] = {u.x, u.y, u.z, u.w};
        float out[4];
#pragma unroll
        for (int q = 0; q < 4; q++) {
            float uv  = uu[q];
            float acc = 0.f;
#pragma unroll
            for (int j = 0; j < SPT; j++) {
                float nr = fmaf(-wim[j], sim[j], fmaf(wre[j], sre[j], uv));
                float ni = fmaf(wre[j], sim[j], wim[j] * sre[j]);
                sre[j] = nr; sim[j] = ni;
                acc = fmaf(cr[j], nr, acc);
                acc = fmaf(-ci[j], ni, acc);
            }
            acc += __shfl_xor_sync(0xffffffffu, acc, 1);
            float yv = fmaf(uv, Dh, acc);
            out[q] = 0.5f * yv * (1.f + erff(yv * 0.7071067811865476f));
        }
        if (half == 0) y4[l] = make_float4(out[0], out[1], out[2], out[3]);
    }
}

// ---------------- GLU GEMM + residual + LayerNorm (in-place h update) ------------
__global__ void glu_kernel(int layer,
                           const float* __restrict__ out_b,
                           const float* __restrict__ ln_g,
                           const float* __restrict__ ln_b) {
    __shared__ float  zt[LT][H_DIM];
    __shared__ float2 mv[LT];

    int bl = blockIdx.x;
    int b  = bl / (L_SEQ / LT);
    int l0 = (bl % (L_SEQ / LT)) * LT;
    int o  = threadIdx.x;

    const float* Wt = g_Wt + layer * 2 * H_DIM * H_DIM;
    float ba = out_b[layer * 2 * H_DIM + o];
    float bg = out_b[layer * 2 * H_DIM + H_DIM + o];

    float a[LT], gg[LT];
#pragma unroll
    for (int l = 0; l < LT; l++) { a[l] = ba; gg[l] = bg; }

    const float* ybase = g_y + b * H_DIM * L_SEQ + l0;
#pragma unroll 2
    for (int k = 0; k < H_DIM; k++) {
        float wa = Wt[k * 2 * H_DIM + o];
        float wg = Wt[k * 2 * H_DIM + H_DIM + o];
        const float4* yr = (const float4*)(ybase + k * L_SEQ);
        float4 y0 = __ldg(yr), y1 = __ldg(yr + 1), y2 = __ldg(yr + 2), y3 = __ldg(yr + 3);
        float yv[LT] = {y0.x, y0.y, y0.z, y0.w, y1.x, y1.y, y1.z, y1.w,
                        y2.x, y2.y, y2.z, y2.w, y3.x, y3.y, y3.z, y3.w};
#pragma unroll
        for (int l = 0; l < LT; l++) {
            a[l]  = fmaf(wa, yv[l], a[l]);
            gg[l] = fmaf(wg, yv[l], gg[l]);
        }
    }

    const float4* hr = (const float4*)(g_h + (b * H_DIM + o) * L_SEQ + l0);
    float4 h0 = hr[0], h1 = hr[1], h2 = hr[2], h3 = hr[3];
    float hv[LT] = {h0.x, h0.y, h0.z, h0.w, h1.x, h1.y, h1.z, h1.w,
                    h2.x, h2.y, h2.z, h2.w, h3.x, h3.y, h3.z, h3.w};
#pragma unroll
    for (int l = 0; l < LT; l++) {
        float sg = 1.f / (1.f + expf(-gg[l]));
        zt[l][o] = fmaf(a[l], sg, hv[l]);     // GLU + residual
    }
    __syncthreads();

    int w = o >> 5, lane = o & 31;
#pragma unroll
    for (int l = w; l < LT; l += 4) {
        float v0 = zt[l][lane], v1 = zt[l][lane + 32];
        float v2 = zt[l][lane + 64], v3 = zt[l][lane + 96];
        float s = v0 + v1 + v2 + v3;
        float q = fmaf(v0, v0, fmaf(v1, v1, fmaf(v2, v2, v3 * v3)));
#pragma unroll
        for (int off = 16; off > 0; off >>= 1) {
            s += __shfl_xor_sync(0xffffffffu, s, off);
            q += __shfl_xor_sync(0xffffffffu, q, off);
        }
        if (lane == 0) {
            float m   = s * (1.0f / H_DIM);
            float var = q * (1.0f / H_DIM) - m * m;
            mv[l] = make_float2(m, rsqrtf(var + 1e-5f));
        }
    }
    __syncthreads();

    float gam = ln_g[layer * H_DIM + o];
    float bet = ln_b[layer * H_DIM + o];
    float res[LT];
#pragma unroll
    for (int l = 0; l < LT; l++)
        res[l] = fmaf((zt[l][o] - mv[l].x) * mv[l].y, gam, bet);

    float4* hw = (float4*)(g_h + (b * H_DIM + o) * L_SEQ + l0);
    hw[0] = make_float4(res[0],  res[1],  res[2],  res[3]);
    hw[1] = make_float4(res[4],  res[5],  res[6],  res[7]);
    hw[2] = make_float4(res[8],  res[9],  res[10], res[11]);
    hw[3] = make_float4(res[12], res[13], res[14], res[15]);
}

// ---------------- mean over L ----------------
__global__ void pool_kernel() {
    int seq = blockIdx.x;
    int t   = threadIdx.x;    // 256 threads
    const float4* r = (const float4*)(g_h + seq * L_SEQ);
    float s = 0.f;
    for (int i = t; i < L_SEQ / 4; i += 256) {
        float4 v = r[i];
        s += v.x + v.y + v.z + v.w;
    }
    __shared__ float sm[256];
    sm[t] = s;
    __syncthreads();
    for (int off = 128; off > 0; off >>= 1) {
        if (t < off) sm[t] += sm[t + off];
        __syncthreads();
    }
    if (t == 0) g_pooled[seq] = sm[0] * (1.f / L_SEQ);
}

// ---------------- head ----------------
__global__ void head_kernel(const float* __restrict__ head_W,
                            const float* __restrict__ head_b,
                            float* __restrict__ out) {
    int t = threadIdx.x;
    if (t >= B_SZ * D_OUT) return;
    int b = t / D_OUT, o = t % D_OUT;
    float s = head_b[o];
    for (int h = 0; h < H_DIM; h++)
        s = fmaf(g_pooled[b * H_DIM + h], head_W[h * D_OUT + o], s);
    out[t] = s;
}

// ---------------- launch ----------------
extern "C" void kernel_launch(void* const* d_in, const int* in_sizes, int n_in,
                              void* d_out, int out_size) {
    const float* x          = (const float*)d_in[0];
    const float* enc_W      = (const float*)d_in[1];
    const float* enc_b      = (const float*)d_in[2];
    const float* log_dt     = (const float*)d_in[3];
    const float* C_re       = (const float*)d_in[4];
    const float* C_im       = (const float*)d_in[5];
    const float* log_A_real = (const float*)d_in[6];
    const float* A_imag     = (const float*)d_in[7];
    const float* Dvec       = (const float*)d_in[8];
    const float* out_W      = (const float*)d_in[9];
    const float* out_b      = (const float*)d_in[10];
    const float* ln_g       = (const float*)d_in[11];
    const float* ln_b       = (const float*)d_in[12];
    const float* head_W     = (const float*)d_in[13];
    const float* head_b     = (const float*)d_in[14];
    float* out = (float*)d_out;

    param_kernel<<<(NL * H_DIM * NC + 127) / 128, 128>>>(log_dt, C_re, C_im,
                                                         log_A_real, A_imag);
    wt_kernel<<<(NL * 2 * H_DIM * H_DIM + 255) / 256, 256>>>(out_W);
    enc_kernel<<<(NSEQ * (L_SEQ / 4)) / 256, 256>>>(x, enc_W, enc_b);

    for (int layer = 0; layer < NL; layer++) {
        pass1_kernel<<<(NSEQ * (CHUNKS - 1) * 2) / 128, 128>>>(layer);
        pass2_kernel<<<(NSEQ * CHUNKS * 2) / 128, 128>>>(layer, Dvec);
        glu_kernel<<<B_SZ * (L_SEQ / LT), 128>>>(layer, out_b, ln_g, ln_b);
    }

    pool_kernel<<<NSEQ, 256>>>();
    head_kernel<<<1, 64>>>(head_W, head_b, out);
}